// round 12
// baseline (speedup 1.0000x reference)
#include <cuda_runtime.h>
#include <cuda_bf16.h>
#include <cstdint>

// Yolov1 loss — persistent kernel, per-warp 2-stage ring staged via
// cp.async.bulk (TMA) + mbarrier, bypassing the per-warp LDG outstanding cap.
// B=16384, cells = 802816 = 25088 tiles of 32 cells (3840 B per tile).
// 444 blocks * 8 warps = 3552 streams; sid = wid*444 + blockIdx.x;
// stream sid: start = sid*7 + min(sid,224), cnt = 7 + (sid<224)  (contiguous run).
// Cell layout: [0:2) conf, [2:10) boxes (NB,4), [10:30) class logits.

#define NBLOCKS  444
#define NTHREADS 256
#define NSTREAMS (NBLOCKS * 8)   // 3552
#define NTILES   25088
#define NEXTRA   (NTILES - NSTREAMS * 7)   // 224
#define TILE_BYTES 3840

__device__ float g_partials[NBLOCKS];
__device__ unsigned int g_done = 0;   // atomicInc mod NBLOCKS -> self-resetting

__device__ __forceinline__ float fsig(float x) {
    float t;
    asm("tanh.approx.f32 %0, %1;" : "=f"(t) : "f"(x * 0.5f));
    return fmaf(t, 0.5f, 0.5f);
}
__device__ __forceinline__ float fsqrt_a(float x) {
    float r;
    asm("sqrt.approx.f32 %0, %1;" : "=f"(r) : "f"(x));
    return r;
}
__device__ __forceinline__ unsigned int smem_u32(const void* p) {
    return (unsigned int)__cvta_generic_to_shared(p);
}

__device__ __forceinline__ void mbar_init(unsigned int bar, unsigned int cnt) {
    asm volatile("mbarrier.init.shared.b64 [%0], %1;" :: "r"(bar), "r"(cnt) : "memory");
}

// Producer: expect 3840 bytes on bar, then one bulk copy gmem->smem.
__device__ __forceinline__ void issue_bulk(unsigned int bar, unsigned int dst,
                                           const void* src) {
    asm volatile("mbarrier.arrive.expect_tx.shared.b64 _, [%0], %1;"
                 :: "r"(bar), "r"((unsigned int)TILE_BYTES) : "memory");
    asm volatile("cp.async.bulk.shared::cta.global.mbarrier::complete_tx::bytes "
                 "[%0], [%1], %2, [%3];"
                 :: "r"(dst), "l"(src), "r"((unsigned int)TILE_BYTES), "r"(bar)
                 : "memory");
}

// Consumer: acquire-wait on phase parity.
__device__ __forceinline__ void mbar_wait(unsigned int bar, unsigned int parity) {
    unsigned int done;
    asm volatile(
        "{\n\t"
        ".reg .pred p;\n\t"
        "mbarrier.try_wait.parity.acquire.cta.shared::cta.b64 p, [%1], %2;\n\t"
        "selp.b32 %0, 1, 0, p;\n\t"
        "}"
        : "=r"(done) : "r"(bar), "r"(parity) : "memory");
    if (!done) {
        asm volatile(
            "{\n\t"
            ".reg .pred P1;\n\t"
            "WAIT_LOOP_%=:\n\t"
            "mbarrier.try_wait.parity.acquire.cta.shared::cta.b64 P1, [%0], %1, 0x989680;\n\t"
            "@P1 bra.uni WAIT_DONE_%=;\n\t"
            "bra.uni WAIT_LOOP_%=;\n\t"
            "WAIT_DONE_%=:\n\t"
            "}"
            :: "r"(bar), "r"(parity) : "memory");
    }
}

// One cell's loss. p = 30 floats in smem; target data already in registers.
__device__ __forceinline__ float cell_loss(const float* __restrict__ p, int t,
                                           float4 tb, int g, int tc)
{
    const int s = t % 49;
    const float xg = (float)(s % 7);
    const float yg = (float)(s / 7);
    const float inv7 = 1.0f / 7.0f;
    const float tox = tb.x, toy = tb.y, tw = tb.z, th = tb.w;

    const float conf0 = fsig(p[0]);
    const float conf1 = fsig(p[1]);
    float pb[2][4];
    #pragma unroll
    for (int nb = 0; nb < 2; nb++)
        #pragma unroll
        for (int k = 0; k < 4; k++)
            pb[nb][k] = fsig(p[2 + nb * 4 + k]);

    float esum = 0.0f, et = 0.0f;
    #pragma unroll
    for (int j = 0; j < 20; j++) {
        const float e = __expf(p[10 + j]);
        esum += e;
        if (j == tc) et = e;
    }
    const float cls_t = __fdividef(et, esum);

    const float tcx = (xg + tox) * inv7;
    const float tcy = (yg + toy) * inv7;
    float iou[2];
    #pragma unroll
    for (int nb = 0; nb < 2; nb++) {
        const float pcx = (xg + pb[nb][0]) * inv7;
        const float pcy = (yg + pb[nb][1]) * inv7;
        const float pw = pb[nb][2], ph = pb[nb][3];
        const float tb_ = fminf(tcx + tw * 0.5f, pcx + pw * 0.5f)
                        - fmaxf(tcx - tw * 0.5f, pcx - pw * 0.5f);
        const float lr_ = fminf(tcy + th * 0.5f, pcy + ph * 0.5f)
                        - fmaxf(tcy - th * 0.5f, pcy - ph * 0.5f);
        const float inter = (tb_ < 0.0f || lr_ < 0.0f) ? 0.0f : tb_ * lr_;
        iou[nb] = __fdividef(inter, tw * th + pw * ph - inter);
    }

    const int best = (iou[1] > iou[0]) ? 1 : 0;
    const float iou_b  = iou[best];
    const float conf_b = best ? conf1 : conf0;

    const float d0 = pb[best][0] - tox;
    const float d1 = pb[best][1] - toy;
    const float d2 = fsqrt_a(pb[best][2]) - fsqrt_a(tw);
    const float d3 = fsqrt_a(pb[best][3]) - fsqrt_a(th);
    const float coord = d0 * d0 + d1 * d1 + d2 * d2 + d3 * d3;

    const float dc = conf_b - iou_b;
    const float dl = 1.0f - cls_t;
    const float obj_loss   = 5.0f * coord + dc * dc + dl * dl;
    const float noobj_loss = 0.5f * (conf0 * conf0 + conf1 * conf1);
    return (g == 1) ? obj_loss : noobj_loss;
}

__global__ __launch_bounds__(NTHREADS, 3)
void yolo_loss_kernel(const float* __restrict__ pred,
                      const int*   __restrict__ grid,
                      const float* __restrict__ tbox,
                      const int*   __restrict__ tcls,
                      float* __restrict__ out)
{
    // 2 stages * 8 warps * 960 floats = 61440 B (16B aligned for bulk copies)
    __shared__ __align__(16) float sp[2 * 8 * 960];
    __shared__ __align__(8) unsigned long long mbar[8 * 2];   // 2 barriers/warp

    const int lane = threadIdx.x & 31;
    const int wid  = threadIdx.x >> 5;

    // Contiguous runs; remainder spread over warp 0 of blocks 0..223.
    const int sid   = wid * NBLOCKS + blockIdx.x;
    const int start = sid * 7 + min(sid, NEXTRA);
    const int cnt   = 7 + (sid < NEXTRA ? 1 : 0);

    float* const s0 = sp + wid * 960;
    float* const s1 = sp + (8 + wid) * 960;
    const unsigned int d0 = smem_u32(s0);
    const unsigned int d1 = smem_u32(s1);
    const unsigned int bar0 = smem_u32(&mbar[wid * 2]);
    const unsigned int bar1 = bar0 + 8;

    const float4* const tbox4 = reinterpret_cast<const float4*>(tbox);

    // ---- init this warp's barriers (warp-private, syncwarp is enough) ----
    if (lane == 0) {
        mbar_init(bar0, 1);
        mbar_init(bar1, 1);
        asm volatile("fence.proxy.async.shared::cta;" ::: "memory");
    }
    __syncwarp();

    // ---- prologue: bulk-load tile 0 into stage 0; prefetch tile-0 targets ----
    if (lane == 0)
        issue_bulk(bar0, d0, pred + (long)start * 960);

    const int c0 = start * 32 + lane;
    float4 tb = __ldg(tbox4 + c0);
    int    g  = __ldg(grid + c0);
    int    tc = __ldg(tcls + c0);

    float v = 0.0f;
    int stage = 0;
    unsigned int ph0 = 0, ph1 = 0;

    for (int it = 0; ; it++) {
        const bool validn = (it + 1 < cnt);
        const int tn = start + it + 1;

        // issue next tile into the alternate stage (read 2 its ago, syncwarp'd)
        if (validn && lane == 0) {
            asm volatile("fence.proxy.async.shared::cta;" ::: "memory");
            issue_bulk(stage ? bar0 : bar1, stage ? d0 : d1,
                       pred + (long)tn * 960);
        }

        // register-prefetch next targets (overlaps current compute)
        float4 tbn = {}; int gn = 0, tcn = 0;
        if (validn) {
            const int cn = tn * 32 + lane;
            tbn = __ldg(tbox4 + cn);
            gn  = __ldg(grid + cn);
            tcn = __ldg(tcls + cn);
        }

        // wait for current stage's bulk copy
        if (stage) { mbar_wait(bar1, ph1); ph1 ^= 1; }
        else       { mbar_wait(bar0, ph0); ph0 ^= 1; }

        const float* p = (stage ? s1 : s0) + lane * 30;
        const int t_cell = (start + it) * 32 + lane;
        v += cell_loss(p, t_cell, tb, g, tc);
        __syncwarp();   // all lanes done reading before this stage is overwritten

        if (!validn) break;
        tb = tbn; g = gn; tc = tcn;
        stage ^= 1;
    }

    // ---- block reduction -> g_partials[blockIdx.x] ----
    #pragma unroll
    for (int o = 16; o; o >>= 1) v += __shfl_down_sync(0xffffffffu, v, o);
    __shared__ float wsum[NTHREADS / 32];
    __shared__ bool s_last;
    if (lane == 0) wsum[wid] = v;
    __syncthreads();
    if (threadIdx.x < NTHREADS / 32) {
        v = wsum[threadIdx.x];
        #pragma unroll
        for (int o = NTHREADS / 64; o; o >>= 1) v += __shfl_down_sync(0xffu, v, o);
        if (threadIdx.x == 0) {
            g_partials[blockIdx.x] = v;
            __threadfence();
            unsigned int prev = atomicInc(&g_done, NBLOCKS - 1);
            s_last = (prev == NBLOCKS - 1);
        }
    }
    __syncthreads();

    // ---- last-arriving block: deterministic final reduction ----
    if (s_last) {
        double acc = 0.0;
        for (int i = threadIdx.x; i < NBLOCKS; i += NTHREADS)
            acc += (double)g_partials[i];
        #pragma unroll
        for (int o = 16; o; o >>= 1) acc += __shfl_down_sync(0xffffffffu, acc, o);
        __shared__ double ws[NTHREADS / 32];
        if (lane == 0) ws[wid] = acc;
        __syncthreads();
        if (threadIdx.x == 0) {
            double sum = 0.0;
            #pragma unroll
            for (int i = 0; i < NTHREADS / 32; i++) sum += ws[i];
            out[0] = (float)(sum / 16384.0);
        }
    }
}

extern "C" void kernel_launch(void* const* d_in, const int* in_sizes, int n_in,
                              void* d_out, int out_size)
{
    const float* pred = (const float*)d_in[0];   // (B, 1470) f32
    const int*   grid = (const int*)  d_in[1];   // (B, 7, 7) i32
    const float* tbox = (const float*)d_in[2];   // (B, 7, 7, 4) f32
    const int*   tcls = (const int*)  d_in[3];   // (B, 7, 7) i32
    float* out = (float*)d_out;

    yolo_loss_kernel<<<NBLOCKS, NTHREADS>>>(pred, grid, tbox, tcls, out);
}